// round 6
// baseline (speedup 1.0000x reference)
#include <cuda_runtime.h>
#include <math.h>

#define TT 1024
#define BB 16
#define SS 2
#define NN 2048
#define BN (BB * NN)     // 32768
#define LL 100

// Scratch: vmem laid out (bn, t).
__device__ float g_vmem[(size_t)BN * TT];

// ---------------------------------------------------------------------------
// Phase 1: EPSP conv, bit-exact fold (oldest spike time first, per synapse,
// then v = a0 + a1), parallel over (bn, t).  UNCHANGED from passing R5.
// ---------------------------------------------------------------------------
__global__ __launch_bounds__(256) void snn_epsp_kernel(
    const float* __restrict__ spikes,   // (T, B, S, N)
    const float* __restrict__ eps)      // (S, L)
{
    __shared__ unsigned smasks[2 * TT];       // [s*TT + t], bit i = neuron n0+i
    __shared__ unsigned sW[2 * 32 * 32];      // [s*1024 + j*32 + w], bit i = t = w*32+i
    __shared__ float sk[2 * LL];

    const int tid = threadIdx.x;
    const int warpId = tid >> 5;
    const int lane = tid & 31;
    const int b  = blockIdx.x >> 6;
    const int n0 = (blockIdx.x & 63) * 32;

    for (int i = tid; i < 2 * LL; i += 256) sk[i] = eps[i];

    for (int idx = warpId; idx < 2 * TT; idx += 8) {
        const int s = idx >> 10;
        const int t = idx & (TT - 1);
        const float val = spikes[(((size_t)t * BB + b) * SS + s) * NN + n0 + lane];
        const unsigned m = __ballot_sync(0xFFFFFFFFu, val != 0.0f);
        if (lane == 0) smasks[s * TT + t] = m;
    }
    __syncthreads();

    {
        const int j = tid & 31;
        const int wbase = tid >> 5;   // 0..7
#pragma unroll
        for (int s = 0; s < 2; ++s) {
#pragma unroll
            for (int k = 0; k < 4; ++k) {
                const int w = wbase + 8 * k;
                unsigned acc = 0;
                const unsigned* mp = &smasks[s * TT + w * 32];
#pragma unroll
                for (int i = 0; i < 32; ++i)
                    acc |= ((mp[i] >> j) & 1u) << i;
                sW[s * 1024 + j * 32 + w] = acc;
            }
        }
    }
    __syncthreads();

#pragma unroll 1
    for (int jj = 0; jj < 4; ++jj) {
        const int j = warpId + jj * 8;
        const size_t obase = ((size_t)(b * NN + n0 + j)) * TT;
        const unsigned* W0 = &sW[j * 32];
        const unsigned* W1 = &sW[1024 + j * 32];
#pragma unroll 1
        for (int chunk = 0; chunk < 32; ++chunk) {
            const int t = chunk * 32 + lane;
            const int tlo = (t >= LL - 1) ? t - (LL - 1) : 0;
            const int wlo = tlo >> 5, whi = t >> 5;
            const unsigned mlo = 0xFFFFFFFFu << (tlo & 31);
            const int r = t & 31;
            const unsigned mhi = (r == 31) ? 0xFFFFFFFFu : ((2u << r) - 1u);

            float a0 = 0.0f;
            for (int w = wlo; w <= whi; ++w) {
                unsigned mm = W0[w];
                if (w == wlo) mm &= mlo;
                if (w == whi) mm &= mhi;
                const int base = w << 5;
                while (mm) {
                    const int i = __ffs(mm) - 1;
                    mm &= mm - 1;
                    a0 = __fadd_rn(a0, sk[t - (base + i)]);
                }
            }
            float a1 = 0.0f;
            for (int w = wlo; w <= whi; ++w) {
                unsigned mm = W1[w];
                if (w == wlo) mm &= mlo;
                if (w == whi) mm &= mhi;
                const int base = w << 5;
                while (mm) {
                    const int i = __ffs(mm) - 1;
                    mm &= mm - 1;
                    a1 = __fadd_rn(a1, sk[LL + t - (base + i)]);
                }
            }
            g_vmem[obase + t] = __fadd_rn(a0, a1);
        }
    }
}

// ---------------------------------------------------------------------------
// Phase 2: sequential threshold + refractory scan.
// Numerics identical to R3/R5 (same fp32 ops, same chain order); only the
// FIFO control flow and addressing are streamlined:
//   - packed float2 entries (time bits, value): one LDL.64 per entry
//   - power-of-2 ring with &127 (no wrap branch), monotone indices
//   - fold unrolled x4: batched loads/muls, chained FSUBs (order preserved)
//   - branchless push
// ---------------------------------------------------------------------------
__global__ __launch_bounds__(128) void snn_scan_kernel(
    const float* __restrict__ refk,     // (L,)
    float* __restrict__ out)            // (T, B, N)
{
    __shared__ float sr[LL];
    for (int i = threadIdx.x; i < LL; i += 128) sr[i] = refk[i];
    __syncthreads();

    const int bn = blockIdx.x * 128 + threadIdx.x;
    const float* pv = g_vmem + (size_t)bn * TT;
    float* po = out + bn;

    float2 fifo[128];               // (te as int bits, nadj)
    int head = 0, tail = 0;

#pragma unroll 1
    for (int t = 0; t < TT; ++t) {
        const float v = __ldg(pv + t);

        // expire: at most one entry per step can reach d >= 100
        if (head != tail) {
            const int te = __float_as_int(fifo[head & 127].x);
            head += (te <= t - LL) ? 1 : 0;
        }

        // buf[0]: fold oldest-first; FSUB chain order == reference
        float racc = 0.0f;
        int i = head;
        int rem = tail - head;
#pragma unroll 1
        for (; rem >= 4; rem -= 4, i += 4) {
            const float2 e0 = fifo[(i + 0) & 127];
            const float2 e1 = fifo[(i + 1) & 127];
            const float2 e2 = fifo[(i + 2) & 127];
            const float2 e3 = fifo[(i + 3) & 127];
            const float p0 = __fmul_rn(e0.y, sr[t - __float_as_int(e0.x)]);
            const float p1 = __fmul_rn(e1.y, sr[t - __float_as_int(e1.x)]);
            const float p2 = __fmul_rn(e2.y, sr[t - __float_as_int(e2.x)]);
            const float p3 = __fmul_rn(e3.y, sr[t - __float_as_int(e3.x)]);
            racc = __fsub_rn(racc, p0);
            racc = __fsub_rn(racc, p1);
            racc = __fsub_rn(racc, p2);
            racc = __fsub_rn(racc, p3);
        }
#pragma unroll 1
        for (; rem > 0; --rem, ++i) {
            const float2 e = fifo[i & 127];
            racc = __fsub_rn(racc, __fmul_rn(e.y, sr[t - __float_as_int(e.x)]));
        }

        const float veff = __fadd_rn(v, racc);
        const float nsp = floorf(fmaxf(veff, 0.0f));

        const float ad = fabsf(__fsub_rn(veff, 1.0f));
        const float sg = __fmul_rn(2.0f, expf(__fmul_rn(ad, -2.0f)));
        const float term = __fmul_rn(sg, veff);
        const float nadj = __fadd_rn(__fsub_rn(nsp, term), term);

        // branchless push: slot tail&127 is never live (window <= 99 < 128)
        float2 en;
        en.x = __int_as_float(t);
        en.y = nadj;
        fifo[tail & 127] = en;
        tail += (nadj != 0.0f) ? 1 : 0;

        po[(size_t)t * BN] = nadj;
    }
}

extern "C" void kernel_launch(void* const* d_in, const int* in_sizes, int n_in,
                              void* d_out, int out_size) {
    const float* spikes = (const float*)d_in[0];   // (T,B,S,N) float32
    const float* eps    = (const float*)d_in[1];   // (2,100)   float32
    const float* refk   = (const float*)d_in[2];   // (100,)    float32
    float* out = (float*)d_out;                    // (T,B,N)   float32

    snn_epsp_kernel<<<BN / 32, 256>>>(spikes, eps);
    snn_scan_kernel<<<BN / 128, 128>>>(refk, out);
}

// round 7
// speedup vs baseline: 2.3899x; 2.3899x over previous
#include <cuda_runtime.h>
#include <math.h>

#define TT 1024
#define BB 16
#define SS 2
#define NN 2048
#define BN (BB * NN)     // 32768
#define LL 100

// vmem scratch, TILED layout: [group = bn/32][t][bn%32]  (coalesced for scan)
__device__ float g_vmem[(size_t)BN * TT];

// ---------------------------------------------------------------------------
// Phase 1: EPSP conv. Bit-exact fold (ascending spike time, per synapse, then
// v = a0 + a1) — same arithmetic as R5, new control flow:
//   - warp = neuron  -> spike-word walks are warp-UNIFORM (no divergence)
//   - per-lane range predicate replaces pre-masking (skipped adds = exact no-op)
//   - results staged in smem, written to g_vmem coalesced in tiled layout
// ---------------------------------------------------------------------------
__global__ __launch_bounds__(256) void snn_epsp_kernel(
    const float* __restrict__ spikes,   // (T, B, S, N)
    const float* __restrict__ eps)      // (S, L)
{
    __shared__ unsigned smasks[2 * TT];     // [s*TT + t], bit i = neuron n0+i
    __shared__ unsigned sW[2 * 32 * 32];    // [s*1024 + j*32 + w], bit i = t=w*32+i
    __shared__ float sk[2 * LL];
    __shared__ float stile[32 * 33];        // 32 t x 32 neurons, padded

    const int tid = threadIdx.x;
    const int warpId = tid >> 5;
    const int lane = tid & 31;
    const int b  = blockIdx.x >> 6;
    const int n0 = (blockIdx.x & 63) * 32;

    for (int i = tid; i < 2 * LL; i += 256) sk[i] = eps[i];

    // ballot spikes -> per-(s,t) neuron masks (coalesced loads)
    for (int idx = warpId; idx < 2 * TT; idx += 8) {
        const int s = idx >> 10;
        const int t = idx & (TT - 1);
        const float val = spikes[(((size_t)t * BB + b) * SS + s) * NN + n0 + lane];
        const unsigned m = __ballot_sync(0xFFFFFFFFu, val != 0.0f);
        if (lane == 0) smasks[s * TT + t] = m;
    }
    __syncthreads();

    // bit-transpose -> per-neuron time-words
    {
        const int j = tid & 31;
        const int wbase = tid >> 5;   // 0..7
#pragma unroll
        for (int s = 0; s < 2; ++s) {
#pragma unroll
            for (int k = 0; k < 4; ++k) {
                const int w = wbase + 8 * k;
                unsigned acc = 0;
                const unsigned* mp = &smasks[s * TT + w * 32];
#pragma unroll
                for (int i = 0; i < 32; ++i)
                    acc |= ((mp[i] >> j) & 1u) << i;
                sW[s * 1024 + j * 32 + w] = acc;
            }
        }
    }
    __syncthreads();

    const size_t gbase = (size_t)blockIdx.x * (32 * TT);

#pragma unroll 1
    for (int c = 0; c < 32; ++c) {
        const int t = c * 32 + lane;
        const int wlo = (c * 32 >= 99) ? ((c * 32 - 99) >> 5) : 0;

#pragma unroll 1
        for (int jj = 0; jj < 4; ++jj) {
            const int j = warpId + jj * 8;
            const unsigned* W0 = &sW[j * 32];
            const unsigned* W1 = &sW[1024 + j * 32];

            float a0 = 0.0f;
#pragma unroll 1
            for (int w = wlo; w <= c; ++w) {
                unsigned mm = W0[w];                 // warp-uniform
                const int base = w << 5;
                while (mm) {
                    const int i = __ffs(mm) - 1;
                    mm &= mm - 1;
                    const int lag = t - (base + i);  // per-lane
                    if ((unsigned)lag <= 99u)
                        a0 = __fadd_rn(a0, sk[lag]);
                }
            }
            float a1 = 0.0f;
#pragma unroll 1
            for (int w = wlo; w <= c; ++w) {
                unsigned mm = W1[w];
                const int base = w << 5;
                while (mm) {
                    const int i = __ffs(mm) - 1;
                    mm &= mm - 1;
                    const int lag = t - (base + i);
                    if ((unsigned)lag <= 99u)
                        a1 = __fadd_rn(a1, sk[LL + lag]);
                }
            }
            stile[lane * 33 + j] = __fadd_rn(a0, a1);
        }
        __syncthreads();
#pragma unroll
        for (int r = 0; r < 4; ++r) {
            const int e = tid + r * 256;             // 0..1023
            g_vmem[gbase + (size_t)c * 1024 + e] = stile[(e >> 5) * 33 + (e & 31)];
        }
        __syncthreads();
    }
}

// ---------------------------------------------------------------------------
// Phase 2: sequential threshold + refractory scan. Numerics identical to
// R3/R5/R6 (same fold order, mul-then-add, expf, straight-through). FIFO in
// dedicated shared memory, TRANSPOSED [slot][tid] -> bank = tid, conflict-free
// for arbitrary per-lane slot indices; no L1 eviction possible.
// ---------------------------------------------------------------------------
#define SCAN_FV_BYTES (128 * 128 * 4)
#define SCAN_FT_BYTES (128 * 128 * 2)
#define SCAN_SMEM (SCAN_FV_BYTES + SCAN_FT_BYTES + 512)

__global__ __launch_bounds__(128) void snn_scan_kernel(
    const float* __restrict__ refk,     // (L,)
    float* __restrict__ out)            // (T, B, N)
{
    extern __shared__ char dyn[];
    float* fV = (float*)dyn;                                        // [128][128]
    unsigned short* fT = (unsigned short*)(dyn + SCAN_FV_BYTES);    // [128][128]
    float* sr = (float*)(dyn + SCAN_FV_BYTES + SCAN_FT_BYTES);     // [LL]

    const int tid = threadIdx.x;
    for (int i = tid; i < LL; i += 128) sr[i] = refk[i];
    __syncthreads();

    const int bn = blockIdx.x * 128 + tid;
    const float* pv = g_vmem + ((size_t)(bn >> 5)) * (32 * TT) + (bn & 31);
    float* po = out + bn;

    int head = 0, tail = 0;

#pragma unroll 1
    for (int t = 0; t < TT; ++t) {
        const float v = pv[(size_t)t * 32];          // coalesced

        // expire: at most one entry per step can reach d >= 100
        if (head != tail) {
            const int te = fT[((head & 127) << 7) + tid];
            head += (te <= t - LL) ? 1 : 0;
        }

        // buf[0]: fold oldest-first; FSUB chain order == reference
        float racc = 0.0f;
#pragma unroll 2
        for (int i = head; i != tail; ++i) {
            const float val = fV[((i & 127) << 7) + tid];
            const int te = fT[((i & 127) << 7) + tid];
            racc = __fsub_rn(racc, __fmul_rn(val, sr[t - te]));
        }

        const float veff = __fadd_rn(v, racc);
        const float nsp = floorf(fmaxf(veff, 0.0f));

        const float ad = fabsf(__fsub_rn(veff, 1.0f));
        const float sg = __fmul_rn(2.0f, expf(__fmul_rn(ad, -2.0f)));
        const float term = __fmul_rn(sg, veff);
        const float nadj = __fadd_rn(__fsub_rn(nsp, term), term);

        // branchless push: slot tail&127 never live (window <= 99 < 128)
        fV[((tail & 127) << 7) + tid] = nadj;
        fT[((tail & 127) << 7) + tid] = (unsigned short)t;
        tail += (nadj != 0.0f) ? 1 : 0;

        po[(size_t)t * BN] = nadj;
    }
}

extern "C" void kernel_launch(void* const* d_in, const int* in_sizes, int n_in,
                              void* d_out, int out_size) {
    const float* spikes = (const float*)d_in[0];   // (T,B,S,N) float32
    const float* eps    = (const float*)d_in[1];   // (2,100)   float32
    const float* refk   = (const float*)d_in[2];   // (100,)    float32
    float* out = (float*)d_out;                    // (T,B,N)   float32

    cudaFuncSetAttribute(snn_scan_kernel,
                         cudaFuncAttributeMaxDynamicSharedMemorySize, SCAN_SMEM);

    snn_epsp_kernel<<<BN / 32, 256>>>(spikes, eps);
    snn_scan_kernel<<<BN / 128, 128, SCAN_SMEM>>>(refk, out);
}

// round 8
// speedup vs baseline: 4.1229x; 1.7251x over previous
#include <cuda_runtime.h>
#include <math.h>

#define TT 1024
#define BB 16
#define SS 2
#define NN 2048
#define BN (BB * NN)     // 32768
#define LL 100
#define SLOTS 128

// vmem scratch, TILED layout: [group = bn/32][t][bn%32]  (coalesced for scan)
__device__ float g_vmem[(size_t)BN * TT];

// ---------------------------------------------------------------------------
// Phase 1: EPSP conv (UNCHANGED from passing R7). Bit-exact fold, warp-uniform
// spike-word walks, tiled coalesced output.
// ---------------------------------------------------------------------------
__global__ __launch_bounds__(256) void snn_epsp_kernel(
    const float* __restrict__ spikes,   // (T, B, S, N)
    const float* __restrict__ eps)      // (S, L)
{
    __shared__ unsigned smasks[2 * TT];
    __shared__ unsigned sW[2 * 32 * 32];
    __shared__ float sk[2 * LL];
    __shared__ float stile[32 * 33];

    const int tid = threadIdx.x;
    const int warpId = tid >> 5;
    const int lane = tid & 31;
    const int b  = blockIdx.x >> 6;
    const int n0 = (blockIdx.x & 63) * 32;

    for (int i = tid; i < 2 * LL; i += 256) sk[i] = eps[i];

    for (int idx = warpId; idx < 2 * TT; idx += 8) {
        const int s = idx >> 10;
        const int t = idx & (TT - 1);
        const float val = spikes[(((size_t)t * BB + b) * SS + s) * NN + n0 + lane];
        const unsigned m = __ballot_sync(0xFFFFFFFFu, val != 0.0f);
        if (lane == 0) smasks[s * TT + t] = m;
    }
    __syncthreads();

    {
        const int j = tid & 31;
        const int wbase = tid >> 5;
#pragma unroll
        for (int s = 0; s < 2; ++s) {
#pragma unroll
            for (int k = 0; k < 4; ++k) {
                const int w = wbase + 8 * k;
                unsigned acc = 0;
                const unsigned* mp = &smasks[s * TT + w * 32];
#pragma unroll
                for (int i = 0; i < 32; ++i)
                    acc |= ((mp[i] >> j) & 1u) << i;
                sW[s * 1024 + j * 32 + w] = acc;
            }
        }
    }
    __syncthreads();

    const size_t gbase = (size_t)blockIdx.x * (32 * TT);

#pragma unroll 1
    for (int c = 0; c < 32; ++c) {
        const int t = c * 32 + lane;
        const int wlo = (c * 32 >= 99) ? ((c * 32 - 99) >> 5) : 0;

#pragma unroll 1
        for (int jj = 0; jj < 4; ++jj) {
            const int j = warpId + jj * 8;
            const unsigned* W0 = &sW[j * 32];
            const unsigned* W1 = &sW[1024 + j * 32];

            float a0 = 0.0f;
#pragma unroll 1
            for (int w = wlo; w <= c; ++w) {
                unsigned mm = W0[w];
                const int base = w << 5;
                while (mm) {
                    const int i = __ffs(mm) - 1;
                    mm &= mm - 1;
                    const int lag = t - (base + i);
                    if ((unsigned)lag <= 99u)
                        a0 = __fadd_rn(a0, sk[lag]);
                }
            }
            float a1 = 0.0f;
#pragma unroll 1
            for (int w = wlo; w <= c; ++w) {
                unsigned mm = W1[w];
                const int base = w << 5;
                while (mm) {
                    const int i = __ffs(mm) - 1;
                    mm &= mm - 1;
                    const int lag = t - (base + i);
                    if ((unsigned)lag <= 99u)
                        a1 = __fadd_rn(a1, sk[LL + lag]);
                }
            }
            stile[lane * 33 + j] = __fadd_rn(a0, a1);
        }
        __syncthreads();
#pragma unroll
        for (int r = 0; r < 4; ++r) {
            const int e = tid + r * 256;
            g_vmem[gbase + (size_t)c * 1024 + e] = stile[(e >> 5) * 33 + (e & 31)];
        }
        __syncthreads();
    }
}

// ---------------------------------------------------------------------------
// Phase 2: dense branch-free refractory scan.
// Time-indexed value ring fV[te & 127][tid] written EVERY step (zeros incl.).
// Each step folds all 99 lags d=99..1 (te ascending == reference order).
// Zero / never-written slots contribute round(0*sr)=+0.0 subtractions, which
// are exact identities -> bit-identical to the compressed fold of R3/R5/R7.
// Fully unrolled; ring wrap via branchless base-pointer select.
// ---------------------------------------------------------------------------
#define SCAN_SMEM (SLOTS * 128 * 4 + 128 * 4)

__global__ __launch_bounds__(128) void snn_scan_kernel(
    const float* __restrict__ refk,     // (L,)
    float* __restrict__ out)            // (T, B, N)
{
    extern __shared__ float dyn[];
    float* fV = dyn;                       // [SLOTS][128]
    float* sv = dyn + SLOTS * 128;         // [LL] (8B-aligned)

    const int tid = threadIdx.x;
    for (int i = tid; i < LL; i += 128) sv[i] = refk[i];
    // zero own column of the ring (thread-private: no sync needed for fV)
#pragma unroll
    for (int s = 0; s < SLOTS; ++s) fV[(s << 7) + tid] = 0.0f;
    __syncthreads();   // for sv

    const int bn = blockIdx.x * 128 + tid;
    const float* pv = g_vmem + ((size_t)(bn >> 5)) * (32 * TT) + (bn & 31);
    float* po = out + bn;

#pragma unroll 1
    for (int t = 0; t < TT; ++t) {
        const float v = pv[(size_t)t * 32];          // coalesced

        const int s0 = (t + 29) & 127;               // slot of te = t-99
        const int jw = 128 - s0;                     // first j that wraps
        const float* colA = fV + ((s0 << 7) + tid);
        const float* colB = colA - (SLOTS << 7);

        float racc = 0.0f;
#pragma unroll
        for (int j = 0; j < 98; j += 2) {
            const int d = 99 - j;
            const float2 s2 = *(const float2*)(sv + (d - 1));  // (sr[d-1], sr[d])
            const float* p0 = (j < jw) ? colA : colB;
            const float* p1 = (j + 1 < jw) ? colA : colB;
            const float v0 = p0[j << 7];
            const float v1 = p1[(j + 1) << 7];
            racc = __fsub_rn(racc, __fmul_rn(v0, s2.y));
            racc = __fsub_rn(racc, __fmul_rn(v1, s2.x));
        }
        {   // j = 98, d = 1
            const float* p = (98 < jw) ? colA : colB;
            racc = __fsub_rn(racc, __fmul_rn(p[98 << 7], sv[1]));
        }

        const float veff = __fadd_rn(v, racc);
        const float nsp = floorf(fmaxf(veff, 0.0f));

        const float ad = fabsf(__fsub_rn(veff, 1.0f));
        const float sg = __fmul_rn(2.0f, expf(__fmul_rn(ad, -2.0f)));
        const float term = __fmul_rn(sg, veff);
        const float nadj = __fadd_rn(__fsub_rn(nsp, term), term);

        // unconditional push (silent steps store exact +0.0)
        fV[((t & 127) << 7) + tid] = nadj;

        po[(size_t)t * BN] = nadj;
    }
}

extern "C" void kernel_launch(void* const* d_in, const int* in_sizes, int n_in,
                              void* d_out, int out_size) {
    const float* spikes = (const float*)d_in[0];   // (T,B,S,N) float32
    const float* eps    = (const float*)d_in[1];   // (2,100)   float32
    const float* refk   = (const float*)d_in[2];   // (100,)    float32
    float* out = (float*)d_out;                    // (T,B,N)   float32

    cudaFuncSetAttribute(snn_scan_kernel,
                         cudaFuncAttributeMaxDynamicSharedMemorySize, SCAN_SMEM);

    snn_epsp_kernel<<<BN / 32, 256>>>(spikes, eps);
    snn_scan_kernel<<<BN / 128, 128, SCAN_SMEM>>>(refk, out);
}